// round 14
// baseline (speedup 1.0000x reference)
#include <cuda_runtime.h>
#include <cuda_bf16.h>
#include <cstdint>

#define KC   1024
#define DD   256
#define BB   32
#define HWD  1024
#define NPIX (BB*HWD)
#define CHW  (DD*HWD)

#define CHUNK 8192      // 128 rows x 32 dims bf16 tile
#define PAIR  16384
#define CAP   16
#define THRESH 1.0f

// Scratch (allocation-free __device__ globals)
__device__ __align__(16) unsigned char g_B1[(size_t)8 * 8 * CHUNK];  // 512KB
__device__ float g_hn[KC];
__device__ __align__(16) unsigned short g_cand[(size_t)NPIX * CAP];
__device__ float g_cscore[(size_t)NPIX * CAP];
__device__ float g_fmax[NPIX];
__device__ int   g_cnt[NPIX];

// ---------------------------------------------------------------------------
__device__ __forceinline__ uint32_t smem_u32(const void* p) {
    uint32_t a;
    asm("{ .reg .u64 t; cvta.to.shared.u64 t, %1; cvt.u32.u64 %0, t; }" : "=r"(a) : "l"(p));
    return a;
}
__device__ __forceinline__ uint32_t swz16(int row, int g) {
    return (uint32_t)((row * 4 + (g ^ ((row >> 1) & 3))) << 4);
}
// monotonic float<->uint encoding (order-preserving for atomicMax)
__device__ __forceinline__ unsigned fenc(float f) {
    unsigned u = __float_as_uint(f);
    return (u & 0x80000000u) ? ~u : (u | 0x80000000u);
}
__device__ __forceinline__ float fdec(unsigned u) {
    unsigned b = (u & 0x80000000u) ? (u & 0x7fffffffu) : ~u;
    return __uint_as_float(b);
}

#define CPASYNC16(d, s) \
    asm volatile("cp.async.cg.shared.global [%0], [%1], 16;" :: "r"(d), "l"(s))
#define CP_COMMIT() asm volatile("cp.async.commit_group;" ::: "memory")
#define CP_WAIT0()  asm volatile("cp.async.wait_group 0;" ::: "memory")

#define LDM4(r, a) \
    asm volatile("ldmatrix.sync.aligned.m8n8.x4.shared.b16 {%0,%1,%2,%3}, [%4];" \
        : "=r"((r)[0]), "=r"((r)[1]), "=r"((r)[2]), "=r"((r)[3]) : "r"(a))

#define MMA16816(c, a, b0, b1) \
    asm volatile("mma.sync.aligned.m16n8k16.row.col.f32.bf16.bf16.f32 " \
        "{%0,%1,%2,%3}, {%4,%5,%6,%7}, {%8,%9}, {%0,%1,%2,%3};" \
        : "+f"((c)[0]), "+f"((c)[1]), "+f"((c)[2]), "+f"((c)[3]) \
        : "r"((a)[0]), "r"((a)[1]), "r"((a)[2]), "r"((a)[3]), "r"(b0), "r"(b1))

// ---------------------------------------------------------------------------
// Prep E: emb (K,D) fp32 -> bf16 swizzled tiles. grid 64 = (nt, chunk).
// ---------------------------------------------------------------------------
__global__ __launch_bounds__(128) void vq_prep_e(const float* __restrict__ emb) {
    int blk = blockIdx.x;
    int nt  = blk >> 3, ch = blk & 7;
    int row = threadIdx.x;
    const float4* er = (const float4*)(emb + (size_t)(nt * 128 + row) * DD + ch * 32);

    unsigned u0[16];
    #pragma unroll
    for (int i = 0; i < 8; i++) {
        float4 v = er[i];
        unsigned a = (unsigned)__bfloat16_as_ushort(__float2bfloat16(v.x));
        unsigned bshort = (unsigned)__bfloat16_as_ushort(__float2bfloat16(v.y));
        unsigned c = (unsigned)__bfloat16_as_ushort(__float2bfloat16(v.z));
        unsigned d = (unsigned)__bfloat16_as_ushort(__float2bfloat16(v.w));
        u0[i*2]   = a | (bshort << 16);
        u0[i*2+1] = c | (d << 16);
    }
    unsigned char* base = g_B1 + (size_t)(nt * 8 + ch) * CHUNK;
    #pragma unroll
    for (int g = 0; g < 4; g++)
        *(uint4*)(base + swz16(row, g)) =
            make_uint4(u0[g*4], u0[g*4+1], u0[g*4+2], u0[g*4+3]);
}

// ---------------------------------------------------------------------------
__global__ void vq_hn_kernel(const float* __restrict__ emb) {
    int k = blockIdx.x * blockDim.x + threadIdx.x;
    if (k >= KC) return;
    const float4* row = (const float4*)(emb + (size_t)k * DD);
    float s = 0.f;
    #pragma unroll 8
    for (int i = 0; i < DD / 4; i++) {
        float4 v = row[i];
        s += v.x * v.x + v.y * v.y + v.z * v.z + v.w * v.w;
    }
    g_hn[k] = 0.5f * s;
}

// ---------------------------------------------------------------------------
// Pass 1 (fused): x -> bf16 conversion direct to smem + z_e copy, then
// coarse bf16 GEMM + candidate selection. 256 CTAs x 256 thr, 2 CTAs/SM.
// (R10 structure + candidate-score & final-max writes)
// ---------------------------------------------------------------------------
__global__ __launch_bounds__(256, 2) void vq_pass1(const float* __restrict__ x,
                                                   float* __restrict__ out_ze) {
    extern __shared__ __align__(1024) unsigned char dyn[];   // A 64KB + 2x16KB ring
    __shared__ float hn_s[KC];
    __shared__ unsigned pixMax[128];
    __shared__ unsigned short lists[128][CAP];
    __shared__ int cnts[128];

    int tid  = threadIdx.x;
    int lane = tid & 31, w = tid >> 5;
    int wm   = w & 1, wn = w >> 1;
    int tile = blockIdx.x;
    int b    = tile >> 3, hw0 = (tile & 7) << 7;
    uint32_t dynA = smem_u32(dyn);
    uint32_t ring = dynA + 65536;

    // B pair 0 prefetch FIRST (overlaps with the conversion below)
    #pragma unroll
    for (int i = 0; i < 4; i++) {
        uint32_t o = (uint32_t)(tid + i * 256) * 16;
        CPASYNC16(ring + o, g_B1 + o);
    }
    CP_COMMIT();

    for (int i = tid; i < KC; i += 256) hn_s[i] = g_hn[i];
    if (tid < 128) { pixMax[tid] = 0u; cnts[tid] = 0; }

    // ---- fused x -> bf16 conversion into resident A smem + z_e copy ----
    {
        int r   = tid & 127;            // pixel row
        int ch0 = (tid >> 7) * 4;       // chunks [ch0, ch0+4)
        const float* xb = x + (size_t)b * CHW + hw0 + r;
        float*       zb = out_ze + (size_t)b * CHW + hw0 + r;
        #pragma unroll
        for (int c4 = 0; c4 < 4; c4++) {
            int ch = ch0 + c4;
            unsigned u0[16];
            #pragma unroll
            for (int i = 0; i < 16; i++) u0[i] = 0;
            #pragma unroll
            for (int d = 0; d < 32; d++) {
                float v = xb[(size_t)(ch * 32 + d) * HWD];
                zb[(size_t)(ch * 32 + d) * HWD] = v;        // fused z_e
                unsigned h = (unsigned)__bfloat16_as_ushort(__float2bfloat16(v));
                u0[d >> 1] |= h << ((d & 1) * 16);
            }
            #pragma unroll
            for (int g = 0; g < 4; g++)
                *(uint4*)(dyn + ch * CHUNK + swz16(r, g)) =
                    make_uint4(u0[g*4], u0[g*4+1], u0[g*4+2], u0[g*4+3]);
        }
    }

    // per-lane ldmatrix offsets
    uint32_t offA[4][2], offB[2][2];
    {
        int rsub = (lane & 7) + ((lane >> 3) & 1) * 8;
        int gsub = lane >> 4;
        #pragma unroll
        for (int mf = 0; mf < 4; mf++)
            #pragma unroll
            for (int ks = 0; ks < 2; ks++)
                offA[mf][ks] = swz16(wm * 64 + mf * 16 + rsub, ks * 2 + gsub);
        #pragma unroll
        for (int nh = 0; nh < 2; nh++)
            #pragma unroll
            for (int ks = 0; ks < 2; ks++)
                offB[nh][ks] = swz16(wn * 32 + nh * 16 + rsub, ks * 2 + gsub);
    }

    float acc[4][4][4];

    for (int s2 = 0; s2 < 32; s2++) {
        CP_WAIT0();
        __syncthreads();          // round 0: also publishes the A conversion
        if (s2 + 1 < 32) {
            uint32_t dst = ring + ((s2 + 1) & 1) * PAIR;
            const unsigned char* src = g_B1 + (size_t)(s2 + 1) * PAIR;
            #pragma unroll
            for (int i = 0; i < 4; i++) {
                uint32_t o = (uint32_t)(tid + i * 256) * 16;
                CPASYNC16(dst + o, src + o);
            }
            CP_COMMIT();
        }
        if ((s2 & 3) == 0) {
            #pragma unroll
            for (int mi = 0; mi < 4; mi++)
                #pragma unroll
                for (int ni = 0; ni < 4; ni++)
                    #pragma unroll
                    for (int e = 0; e < 4; e++) acc[mi][ni][e] = 0.f;
        }
        uint32_t sbuf = ring + (s2 & 1) * PAIR;
        #pragma unroll
        for (int h = 0; h < 2; h++) {
            uint32_t sa = dynA + ((2 * s2 + h) & 7) * CHUNK;
            uint32_t sb = sbuf + h * CHUNK;
            #pragma unroll
            for (int ks = 0; ks < 2; ks++) {
                uint32_t Ar[4][4], Br[2][4];
                #pragma unroll
                for (int mf = 0; mf < 4; mf++) LDM4(Ar[mf], sa + offA[mf][ks]);
                #pragma unroll
                for (int nh = 0; nh < 2; nh++) LDM4(Br[nh], sb + offB[nh][ks]);
                #pragma unroll
                for (int mi = 0; mi < 4; mi++)
                    #pragma unroll
                    for (int ni = 0; ni < 4; ni++)
                        MMA16816(acc[mi][ni], Ar[mi],
                                 Br[ni >> 1][ni & 1], Br[ni >> 1][(ni & 1) + 2]);
            }
        }

        if ((s2 & 3) == 3) {
            int nt = s2 >> 2;
            // 1) per-pixel running max via monotonic atomicMax
            #pragma unroll
            for (int mi = 0; mi < 4; mi++)
                #pragma unroll
                for (int eh = 0; eh < 2; eh++) {
                    int p = wm * 64 + mi * 16 + eh * 8 + (lane >> 2);
                    float bs = -3.0e38f;
                    #pragma unroll
                    for (int ni = 0; ni < 4; ni++)
                        #pragma unroll
                        for (int e2 = 0; e2 < 2; e2++) {
                            int code = nt * 128 + wn * 32 + ni * 8 + (lane & 3) * 2 + e2;
                            bs = fmaxf(bs, acc[mi][ni][eh * 2 + e2] - hn_s[code]);
                        }
                    atomicMax(&pixMax[p], fenc(bs));
                }
            __syncthreads();
            // 2) append candidates (code + coarse score) within THRESH
            #pragma unroll
            for (int mi = 0; mi < 4; mi++)
                #pragma unroll
                for (int eh = 0; eh < 2; eh++) {
                    int p = wm * 64 + mi * 16 + eh * 8 + (lane >> 2);
                    float thr = fdec(pixMax[p]) - THRESH;
                    #pragma unroll
                    for (int ni = 0; ni < 4; ni++)
                        #pragma unroll
                        for (int e2 = 0; e2 < 2; e2++) {
                            int code = nt * 128 + wn * 32 + ni * 8 + (lane & 3) * 2 + e2;
                            float v = acc[mi][ni][eh * 2 + e2] - hn_s[code];
                            if (v >= thr) {
                                int slot = atomicAdd(&cnts[p], 1);
                                if (slot < CAP) {
                                    lists[p][slot] = (unsigned short)code;
                                    g_cscore[(size_t)(tile * 128 + p) * CAP + slot] = v;
                                }
                            }
                        }
                }
        }
    }

    __syncthreads();
    if (tid < 128) {
        int pix = tile * 128 + tid;
        g_cnt[pix]  = cnts[tid];
        g_fmax[pix] = fdec(pixMax[tid]);
        uint4* d = (uint4*)(g_cand + (size_t)pix * CAP);
        const uint4* sp = (const uint4*)lists[tid];
        d[0] = sp[0];
        d[1] = sp[1];
    }
}

// ---------------------------------------------------------------------------
// Finisher v3: filter candidates by FINAL coarse max, rescore survivors only,
// fused z_q. 1024 blocks x 128 thr, 32 pixels/block, full 128B coalescing.
// ---------------------------------------------------------------------------
__global__ __launch_bounds__(128) void vq_finish(const float* __restrict__ x,
                                                 const float* __restrict__ emb,
                                                 float* __restrict__ out_zq) {
    extern __shared__ __align__(16) float xs[];   // [32][257] fp32

    int blk = blockIdx.x;
    int b = blk >> 5, hw0 = (blk & 31) << 5;      // 32 blocks/batch, 32 px each
    int tid = threadIdx.x, lane = tid & 31, w = tid >> 5;

    // stage x tile: 32 px x 256 dims; lanes span 32 consecutive px -> 128B txns
    const float* xb = x + (size_t)b * CHW + hw0;
    #pragma unroll 8
    for (int i = 0; i < 64; i++) {
        int idx = tid + i * 128;
        int p = idx & 31, d = idx >> 5;
        xs[p * 257 + d] = __ldg(xb + (size_t)d * HWD + p);
    }
    __syncthreads();

    // rescore survivors: warp w owns pixels w*8 .. w*8+7
    int myidx[8];
    #pragma unroll
    for (int j = 0; j < 8; j++) {
        int p = w * 8 + j;
        int pix = b * HWD + hw0 + p;
        const float* xp = xs + p * 257;
        int cnt = g_cnt[pix];
        float best = -3.0e38f;
        int   bidx = KC;
        if (cnt <= CAP) {
            float fthr = g_fmax[pix] - THRESH;
            for (int q = 0; q < cnt; q++) {
                if (g_cscore[(size_t)pix * CAP + q] < fthr) continue;  // pruned
                int code = g_cand[(size_t)pix * CAP + q];
                float a = 0.f;
                #pragma unroll
                for (int i = 0; i < 8; i++)
                    a += xp[i * 32 + lane] * __ldg(&emb[(size_t)code * DD + i * 32 + lane]);
                #pragma unroll
                for (int off = 16; off; off >>= 1)
                    a += __shfl_xor_sync(0xffffffff, a, off);
                float s = a - __ldg(&g_hn[code]);
                if (s > best || (s == best && code < bidx)) { best = s; bidx = code; }
            }
        } else {
            for (int code = 0; code < KC; code++) {   // overflow fallback (rare)
                float a = 0.f;
                #pragma unroll
                for (int i = 0; i < 8; i++)
                    a += xp[i * 32 + lane] * __ldg(&emb[(size_t)code * DD + i * 32 + lane]);
                #pragma unroll
                for (int off = 16; off; off >>= 1)
                    a += __shfl_xor_sync(0xffffffff, a, off);
                float s = a - __ldg(&g_hn[code]);
                if (s > best || (s == best && code < bidx)) { best = s; bidx = code; }
            }
        }
        myidx[j] = bidx;
    }

    // gather winning emb rows into warp-private xs rows (no sync needed)
    #pragma unroll
    for (int j = 0; j < 8; j++) {
        int p = w * 8 + j;
        const float* er = emb + (size_t)myidx[j] * DD;
        #pragma unroll
        for (int i = 0; i < 8; i++)
            xs[p * 257 + i * 32 + lane] = __ldg(er + i * 32 + lane);
    }
    __syncthreads();

    // write z_q: lanes span 32 consecutive px -> 128B coalesced stores
    float* ob = out_zq + (size_t)b * CHW + hw0;
    #pragma unroll 8
    for (int i = 0; i < 64; i++) {
        int idx = tid + i * 128;
        int p = idx & 31, c = idx >> 5;
        ob[(size_t)c * HWD + p] = xs[p * 257 + c];
    }
}

// ---------------------------------------------------------------------------
extern "C" void kernel_launch(void* const* d_in, const int* in_sizes, int n_in,
                              void* d_out, int out_size) {
    const float* x   = (const float*)d_in[0];
    const float* emb = (const float*)d_in[1];
    float* out_ze = (float*)d_out;
    float* out_zq = out_ze + (size_t)NPIX * DD;

    const int p1_smem = 65536 + 2 * PAIR;     // 98304
    const int fin_smem = 32 * 257 * 4;        // 32896
    cudaFuncSetAttribute(vq_pass1, cudaFuncAttributeMaxDynamicSharedMemorySize, p1_smem);
    cudaFuncSetAttribute(vq_finish, cudaFuncAttributeMaxDynamicSharedMemorySize, fin_smem);

    vq_prep_e<<<64, 128>>>(emb);
    vq_hn_kernel<<<KC / 256, 256>>>(emb);
    vq_pass1<<<256, 256, p1_smem>>>(x, out_ze);
    vq_finish<<<1024, 128, fin_smem>>>(x, emb, out_zq);
}

// round 15
// speedup vs baseline: 1.0984x; 1.0984x over previous
#include <cuda_runtime.h>
#include <cuda_bf16.h>
#include <cstdint>

#define KC   1024
#define DD   256
#define BB   32
#define HWD  1024
#define NPIX (BB*HWD)
#define CHW  (DD*HWD)

#define CHUNK 8192      // 128 rows x 32 dims bf16 tile
#define PAIR  16384
#define CAP   16
#define THRESH 1.0f

// Scratch (allocation-free __device__ globals)
__device__ __align__(16) unsigned char g_B1[(size_t)8 * 8 * CHUNK];  // 512KB
__device__ float g_hn[KC];
__device__ __align__(16) unsigned short g_cand[(size_t)NPIX * CAP];
__device__ float g_cscore[(size_t)NPIX * CAP];
__device__ float g_fmax[NPIX];
__device__ int   g_cnt[NPIX];

// ---------------------------------------------------------------------------
__device__ __forceinline__ uint32_t smem_u32(const void* p) {
    uint32_t a;
    asm("{ .reg .u64 t; cvta.to.shared.u64 t, %1; cvt.u32.u64 %0, t; }" : "=r"(a) : "l"(p));
    return a;
}
__device__ __forceinline__ uint32_t swz16(int row, int g) {
    return (uint32_t)((row * 4 + (g ^ ((row >> 1) & 3))) << 4);
}
// monotonic float<->uint encoding (order-preserving for atomicMax)
__device__ __forceinline__ unsigned fenc(float f) {
    unsigned u = __float_as_uint(f);
    return (u & 0x80000000u) ? ~u : (u | 0x80000000u);
}
__device__ __forceinline__ float fdec(unsigned u) {
    unsigned b = (u & 0x80000000u) ? (u & 0x7fffffffu) : ~u;
    return __uint_as_float(b);
}

#define CPASYNC16(d, s) \
    asm volatile("cp.async.cg.shared.global [%0], [%1], 16;" :: "r"(d), "l"(s))
#define CP_COMMIT() asm volatile("cp.async.commit_group;" ::: "memory")
#define CP_WAIT0()  asm volatile("cp.async.wait_group 0;" ::: "memory")

#define LDM4(r, a) \
    asm volatile("ldmatrix.sync.aligned.m8n8.x4.shared.b16 {%0,%1,%2,%3}, [%4];" \
        : "=r"((r)[0]), "=r"((r)[1]), "=r"((r)[2]), "=r"((r)[3]) : "r"(a))

#define MMA16816(c, a, b0, b1) \
    asm volatile("mma.sync.aligned.m16n8k16.row.col.f32.bf16.bf16.f32 " \
        "{%0,%1,%2,%3}, {%4,%5,%6,%7}, {%8,%9}, {%0,%1,%2,%3};" \
        : "+f"((c)[0]), "+f"((c)[1]), "+f"((c)[2]), "+f"((c)[3]) \
        : "r"((a)[0]), "r"((a)[1]), "r"((a)[2]), "r"((a)[3]), "r"(b0), "r"(b1))

// ---------------------------------------------------------------------------
// Prep E: emb (K,D) fp32 -> bf16 swizzled tiles. grid 64 = (nt, chunk).
// ---------------------------------------------------------------------------
__global__ __launch_bounds__(128) void vq_prep_e(const float* __restrict__ emb) {
    int blk = blockIdx.x;
    int nt  = blk >> 3, ch = blk & 7;
    int row = threadIdx.x;
    const float4* er = (const float4*)(emb + (size_t)(nt * 128 + row) * DD + ch * 32);

    unsigned u0[16];
    #pragma unroll
    for (int i = 0; i < 8; i++) {
        float4 v = er[i];
        unsigned a = (unsigned)__bfloat16_as_ushort(__float2bfloat16(v.x));
        unsigned bshort = (unsigned)__bfloat16_as_ushort(__float2bfloat16(v.y));
        unsigned c = (unsigned)__bfloat16_as_ushort(__float2bfloat16(v.z));
        unsigned d = (unsigned)__bfloat16_as_ushort(__float2bfloat16(v.w));
        u0[i*2]   = a | (bshort << 16);
        u0[i*2+1] = c | (d << 16);
    }
    unsigned char* base = g_B1 + (size_t)(nt * 8 + ch) * CHUNK;
    #pragma unroll
    for (int g = 0; g < 4; g++)
        *(uint4*)(base + swz16(row, g)) =
            make_uint4(u0[g*4], u0[g*4+1], u0[g*4+2], u0[g*4+3]);
}

// ---------------------------------------------------------------------------
__global__ void vq_hn_kernel(const float* __restrict__ emb) {
    int k = blockIdx.x * blockDim.x + threadIdx.x;
    if (k >= KC) return;
    const float4* row = (const float4*)(emb + (size_t)k * DD);
    float s = 0.f;
    #pragma unroll 8
    for (int i = 0; i < DD / 4; i++) {
        float4 v = row[i];
        s += v.x * v.x + v.y * v.y + v.z * v.z + v.w * v.w;
    }
    g_hn[k] = 0.5f * s;
}

// ---------------------------------------------------------------------------
// Pass 1 (fused): x -> bf16 conversion direct to smem + z_e copy, then
// coarse bf16 GEMM + candidate selection. 256 CTAs x 256 thr, 2 CTAs/SM.
// (R14 passing version: R10 structure + cscore/fmax writes)
// ---------------------------------------------------------------------------
__global__ __launch_bounds__(256, 2) void vq_pass1(const float* __restrict__ x,
                                                   float* __restrict__ out_ze) {
    extern __shared__ __align__(1024) unsigned char dyn[];   // A 64KB + 2x16KB ring
    __shared__ float hn_s[KC];
    __shared__ unsigned pixMax[128];
    __shared__ unsigned short lists[128][CAP];
    __shared__ int cnts[128];

    int tid  = threadIdx.x;
    int lane = tid & 31, w = tid >> 5;
    int wm   = w & 1, wn = w >> 1;
    int tile = blockIdx.x;
    int b    = tile >> 3, hw0 = (tile & 7) << 7;
    uint32_t dynA = smem_u32(dyn);
    uint32_t ring = dynA + 65536;

    // B pair 0 prefetch FIRST (overlaps with the conversion below)
    #pragma unroll
    for (int i = 0; i < 4; i++) {
        uint32_t o = (uint32_t)(tid + i * 256) * 16;
        CPASYNC16(ring + o, g_B1 + o);
    }
    CP_COMMIT();

    for (int i = tid; i < KC; i += 256) hn_s[i] = g_hn[i];
    if (tid < 128) { pixMax[tid] = 0u; cnts[tid] = 0; }

    // ---- fused x -> bf16 conversion into resident A smem + z_e copy ----
    {
        int r   = tid & 127;            // pixel row
        int ch0 = (tid >> 7) * 4;       // chunks [ch0, ch0+4)
        const float* xb = x + (size_t)b * CHW + hw0 + r;
        float*       zb = out_ze + (size_t)b * CHW + hw0 + r;
        #pragma unroll
        for (int c4 = 0; c4 < 4; c4++) {
            int ch = ch0 + c4;
            unsigned u0[16];
            #pragma unroll
            for (int i = 0; i < 16; i++) u0[i] = 0;
            #pragma unroll
            for (int d = 0; d < 32; d++) {
                float v = xb[(size_t)(ch * 32 + d) * HWD];
                zb[(size_t)(ch * 32 + d) * HWD] = v;        // fused z_e
                unsigned h = (unsigned)__bfloat16_as_ushort(__float2bfloat16(v));
                u0[d >> 1] |= h << ((d & 1) * 16);
            }
            #pragma unroll
            for (int g = 0; g < 4; g++)
                *(uint4*)(dyn + ch * CHUNK + swz16(r, g)) =
                    make_uint4(u0[g*4], u0[g*4+1], u0[g*4+2], u0[g*4+3]);
        }
    }

    // per-lane ldmatrix offsets
    uint32_t offA[4][2], offB[2][2];
    {
        int rsub = (lane & 7) + ((lane >> 3) & 1) * 8;
        int gsub = lane >> 4;
        #pragma unroll
        for (int mf = 0; mf < 4; mf++)
            #pragma unroll
            for (int ks = 0; ks < 2; ks++)
                offA[mf][ks] = swz16(wm * 64 + mf * 16 + rsub, ks * 2 + gsub);
        #pragma unroll
        for (int nh = 0; nh < 2; nh++)
            #pragma unroll
            for (int ks = 0; ks < 2; ks++)
                offB[nh][ks] = swz16(wn * 32 + nh * 16 + rsub, ks * 2 + gsub);
    }

    float acc[4][4][4];

    for (int s2 = 0; s2 < 32; s2++) {
        CP_WAIT0();
        __syncthreads();          // round 0: also publishes the A conversion
        if (s2 + 1 < 32) {
            uint32_t dst = ring + ((s2 + 1) & 1) * PAIR;
            const unsigned char* src = g_B1 + (size_t)(s2 + 1) * PAIR;
            #pragma unroll
            for (int i = 0; i < 4; i++) {
                uint32_t o = (uint32_t)(tid + i * 256) * 16;
                CPASYNC16(dst + o, src + o);
            }
            CP_COMMIT();
        }
        if ((s2 & 3) == 0) {
            #pragma unroll
            for (int mi = 0; mi < 4; mi++)
                #pragma unroll
                for (int ni = 0; ni < 4; ni++)
                    #pragma unroll
                    for (int e = 0; e < 4; e++) acc[mi][ni][e] = 0.f;
        }
        uint32_t sbuf = ring + (s2 & 1) * PAIR;
        #pragma unroll
        for (int h = 0; h < 2; h++) {
            uint32_t sa = dynA + ((2 * s2 + h) & 7) * CHUNK;
            uint32_t sb = sbuf + h * CHUNK;
            #pragma unroll
            for (int ks = 0; ks < 2; ks++) {
                uint32_t Ar[4][4], Br[2][4];
                #pragma unroll
                for (int mf = 0; mf < 4; mf++) LDM4(Ar[mf], sa + offA[mf][ks]);
                #pragma unroll
                for (int nh = 0; nh < 2; nh++) LDM4(Br[nh], sb + offB[nh][ks]);
                #pragma unroll
                for (int mi = 0; mi < 4; mi++)
                    #pragma unroll
                    for (int ni = 0; ni < 4; ni++)
                        MMA16816(acc[mi][ni], Ar[mi],
                                 Br[ni >> 1][ni & 1], Br[ni >> 1][(ni & 1) + 2]);
            }
        }

        if ((s2 & 3) == 3) {
            int nt = s2 >> 2;
            // 1) per-pixel running max via monotonic atomicMax
            #pragma unroll
            for (int mi = 0; mi < 4; mi++)
                #pragma unroll
                for (int eh = 0; eh < 2; eh++) {
                    int p = wm * 64 + mi * 16 + eh * 8 + (lane >> 2);
                    float bs = -3.0e38f;
                    #pragma unroll
                    for (int ni = 0; ni < 4; ni++)
                        #pragma unroll
                        for (int e2 = 0; e2 < 2; e2++) {
                            int code = nt * 128 + wn * 32 + ni * 8 + (lane & 3) * 2 + e2;
                            bs = fmaxf(bs, acc[mi][ni][eh * 2 + e2] - hn_s[code]);
                        }
                    atomicMax(&pixMax[p], fenc(bs));
                }
            __syncthreads();
            // 2) append candidates (code + coarse score) within THRESH
            #pragma unroll
            for (int mi = 0; mi < 4; mi++)
                #pragma unroll
                for (int eh = 0; eh < 2; eh++) {
                    int p = wm * 64 + mi * 16 + eh * 8 + (lane >> 2);
                    float thr = fdec(pixMax[p]) - THRESH;
                    #pragma unroll
                    for (int ni = 0; ni < 4; ni++)
                        #pragma unroll
                        for (int e2 = 0; e2 < 2; e2++) {
                            int code = nt * 128 + wn * 32 + ni * 8 + (lane & 3) * 2 + e2;
                            float v = acc[mi][ni][eh * 2 + e2] - hn_s[code];
                            if (v >= thr) {
                                int slot = atomicAdd(&cnts[p], 1);
                                if (slot < CAP) {
                                    lists[p][slot] = (unsigned short)code;
                                    g_cscore[(size_t)(tile * 128 + p) * CAP + slot] = v;
                                }
                            }
                        }
                }
        }
    }

    __syncthreads();
    if (tid < 128) {
        int pix = tile * 128 + tid;
        g_cnt[pix]  = cnts[tid];
        g_fmax[pix] = fdec(pixMax[tid]);
        uint4* d = (uint4*)(g_cand + (size_t)pix * CAP);
        const uint4* sp = (const uint4*)lists[tid];
        d[0] = sp[0];
        d[1] = sp[1];
    }
}

// ---------------------------------------------------------------------------
// Finisher v4: R13 shape (2048 blocks x 128 thr, 16 px, 2 syncs) + final-max
// candidate pruning before rescore.
// ---------------------------------------------------------------------------
__global__ __launch_bounds__(128) void vq_finish(const float* __restrict__ x,
                                                 const float* __restrict__ emb,
                                                 float* __restrict__ out_zq) {
    extern __shared__ __align__(16) float xs[];   // [16][257] fp32

    int blk = blockIdx.x;
    int b = blk >> 6, hw0 = (blk & 63) << 4;      // 64 blocks/batch, 16 px each
    int tid = threadIdx.x, lane = tid & 31, w = tid >> 5;

    // stage x tile: 16 pixels x 256 dims, 32 independent loads per thread
    const float* xb = x + (size_t)b * CHW + hw0;
    #pragma unroll 8
    for (int i = 0; i < 32; i++) {
        int idx = tid + i * 128;
        int p = idx & 15, d = idx >> 4;
        xs[p * 257 + d] = __ldg(xb + (size_t)d * HWD + p);
    }
    __syncthreads();

    // rescore survivors only: warp w owns pixels w*4 .. w*4+3
    int myidx[4];
    #pragma unroll
    for (int j = 0; j < 4; j++) {
        int p = w * 4 + j;
        int pix = b * HWD + hw0 + p;
        const float* xp = xs + p * 257;
        int cnt = g_cnt[pix];
        float best = -3.0e38f;
        int   bidx = KC;
        if (cnt <= CAP) {
            float fthr = g_fmax[pix] - THRESH;
            for (int q = 0; q < cnt; q++) {
                if (g_cscore[(size_t)pix * CAP + q] < fthr) continue;  // pruned
                int code = g_cand[(size_t)pix * CAP + q];
                float a = 0.f;
                #pragma unroll
                for (int i = 0; i < 8; i++)
                    a += xp[i * 32 + lane] * __ldg(&emb[(size_t)code * DD + i * 32 + lane]);
                #pragma unroll
                for (int off = 16; off; off >>= 1)
                    a += __shfl_xor_sync(0xffffffff, a, off);
                float s = a - __ldg(&g_hn[code]);
                if (s > best || (s == best && code < bidx)) { best = s; bidx = code; }
            }
        } else {
            for (int code = 0; code < KC; code++) {   // overflow fallback (rare)
                float a = 0.f;
                #pragma unroll
                for (int i = 0; i < 8; i++)
                    a += xp[i * 32 + lane] * __ldg(&emb[(size_t)code * DD + i * 32 + lane]);
                #pragma unroll
                for (int off = 16; off; off >>= 1)
                    a += __shfl_xor_sync(0xffffffff, a, off);
                float s = a - __ldg(&g_hn[code]);
                if (s > best || (s == best && code < bidx)) { best = s; bidx = code; }
            }
        }
        myidx[j] = bidx;
    }

    // gather winning emb rows into the SAME warp-private xs slots (no sync
    // needed: each warp reads/writes only its own 4 pixels' rows)
    #pragma unroll
    for (int j = 0; j < 4; j++) {
        int p = w * 4 + j;
        const float* er = emb + (size_t)myidx[j] * DD;
        #pragma unroll
        for (int i = 0; i < 8; i++)
            xs[p * 257 + i * 32 + lane] = __ldg(er + i * 32 + lane);
    }
    __syncthreads();

    // write z_q: 32 independent coalesced stores per thread
    float* ob = out_zq + (size_t)b * CHW + hw0;
    #pragma unroll 8
    for (int i = 0; i < 32; i++) {
        int idx = tid + i * 128;
        int p = idx & 15, c = idx >> 4;
        ob[(size_t)c * HWD + p] = xs[p * 257 + c];
    }
}

// ---------------------------------------------------------------------------
extern "C" void kernel_launch(void* const* d_in, const int* in_sizes, int n_in,
                              void* d_out, int out_size) {
    const float* x   = (const float*)d_in[0];
    const float* emb = (const float*)d_in[1];
    float* out_ze = (float*)d_out;
    float* out_zq = out_ze + (size_t)NPIX * DD;

    const int p1_smem = 65536 + 2 * PAIR;     // 98304
    const int fin_smem = 16 * 257 * 4;        // 16448
    cudaFuncSetAttribute(vq_pass1, cudaFuncAttributeMaxDynamicSharedMemorySize, p1_smem);
    cudaFuncSetAttribute(vq_finish, cudaFuncAttributeMaxDynamicSharedMemorySize, fin_smem);

    vq_prep_e<<<64, 128>>>(emb);
    vq_hn_kernel<<<KC / 256, 256>>>(emb);
    vq_pass1<<<256, 256, p1_smem>>>(x, out_ze);
    vq_finish<<<2048, 128, fin_smem>>>(x, emb, out_zq);
}